// round 5
// baseline (speedup 1.0000x reference)
#include <cuda_runtime.h>
#include <cuda_bf16.h>
#include <math.h>

// Problem constants
#define B_   16
#define T_   2048
#define E_   1024
#define H_   64

// Scratch for q,k,v projections (device globals: no allocation allowed)
__device__ float g_q[B_ * T_ * H_];
__device__ float g_k[B_ * T_ * H_];
__device__ float g_v[B_ * T_ * H_];

// ---------------------------------------------------------------------------
// Kernel 1: QKV projection.  out[which] = x @ W,  x:[B*T, E], W:[E, H]
// Tiled SGEMM: BM=64, BN=64(=H), BK=16, 256 threads, 4x4 register tile.
// grid = (M/64, 3), blockIdx.y selects (Wk->g_k, Wq->g_q, Wv->g_v)
// ---------------------------------------------------------------------------
__global__ __launch_bounds__(256) void proj_kernel(
    const float* __restrict__ x,
    const float* __restrict__ Wk,
    const float* __restrict__ Wq,
    const float* __restrict__ Wv)
{
    __shared__ float xsT[16][68];   // [kk][row], padded to 68 for bank spread
    __shared__ float ws [16][64];   // [kk][col]

    const float* W;
    float* out;
    if (blockIdx.y == 0)      { W = Wk; out = g_k; }
    else if (blockIdx.y == 1) { W = Wq; out = g_q; }
    else                      { W = Wv; out = g_v; }

    const int tid = threadIdx.x;
    const int ty = tid >> 4;          // 0..15
    const int tx = tid & 15;          // 0..15
    const int row0 = ty * 4;
    const int col0 = tx * 4;
    const long rowBase = (long)blockIdx.x * 64;

    // loader indices
    const int xr = tid >> 2;          // 0..63 (row within tile)
    const int xc = (tid & 3) * 4;     // k-offset within 16
    const int wr = tid >> 4;          // 0..15 (k row)
    const int wc = (tid & 15) * 4;    // col offset

    float acc[4][4] = {};

    for (int k0 = 0; k0 < E_; k0 += 16) {
        // load x tile (64 rows x 16 k) transposed into smem
        float4 xv = *(const float4*)&x[(rowBase + xr) * E_ + k0 + xc];
        xsT[xc + 0][xr] = xv.x;
        xsT[xc + 1][xr] = xv.y;
        xsT[xc + 2][xr] = xv.z;
        xsT[xc + 3][xr] = xv.w;
        // load W tile (16 k x 64 cols)
        *(float4*)&ws[wr][wc] = *(const float4*)&W[(long)(k0 + wr) * H_ + wc];
        __syncthreads();

        #pragma unroll
        for (int kk = 0; kk < 16; kk++) {
            float4 a4 = *(const float4*)&xsT[kk][row0];
            float4 b4 = *(const float4*)&ws[kk][col0];
            float a[4] = {a4.x, a4.y, a4.z, a4.w};
            float b[4] = {b4.x, b4.y, b4.z, b4.w};
            #pragma unroll
            for (int i = 0; i < 4; i++)
                #pragma unroll
                for (int j = 0; j < 4; j++)
                    acc[i][j] += a[i] * b[j];
        }
        __syncthreads();
    }

    #pragma unroll
    for (int i = 0; i < 4; i++) {
        *(float4*)&out[(rowBase + row0 + i) * H_ + col0] =
            make_float4(acc[i][0], acc[i][1], acc[i][2], acc[i][3]);
    }
}

// ---------------------------------------------------------------------------
// Kernel 2: causal flash attention over head dim 64.
// One block = one (batch, 64-query tile). 256 threads, 4x4 register tiles.
// Iterates key tiles j = 0..qi with online softmax.
// smem: qs[64][64], ks[64][68], vs[64][64], ps[64][68]  (dynamic, 67584 B)
// ---------------------------------------------------------------------------
#define KS_ 68
#define PS_ 68
#define ATTN_SMEM ((64*64 + 64*KS_ + 64*64 + 64*PS_) * 4)

__global__ __launch_bounds__(256) void attn_kernel(float* __restrict__ out)
{
    extern __shared__ float sm[];
    float* qs = sm;                    // 64*64
    float* ks = qs + 64 * 64;          // 64*KS_
    float* vs = ks + 64 * KS_;         // 64*64
    float* ps = vs + 64 * 64;          // 64*PS_

    const int qi = blockIdx.x;         // query tile 0..31
    const int b  = blockIdx.y;         // batch 0..15
    const int tid = threadIdx.x;
    const int ty = tid >> 4;
    const int tx = tid & 15;
    const int row0 = ty * 4;
    const int col0 = tx * 4;

    const float* qb = g_q + ((long)b * T_ + (long)qi * 64) * H_;
    const float* kb = g_k + (long)b * T_ * H_;
    const float* vb = g_v + (long)b * T_ * H_;

    // load q tile (64x64), float4 coalesced
    #pragma unroll
    for (int i = 0; i < 4; i++) {
        int idx = (tid + i * 256) * 4;
        int r = idx >> 6, c = idx & 63;
        *(float4*)&qs[r * 64 + c] = *(const float4*)&qb[r * 64 + c];
    }

    float acc[4][4] = {};
    float m_i[4], l_i[4];
    #pragma unroll
    for (int i = 0; i < 4; i++) { m_i[i] = -INFINITY; l_i[i] = 0.0f; }

    const float scale = 0.125f;  // 64^-0.5

    for (int j = 0; j <= qi; j++) {
        __syncthreads();  // previous iteration done with ks/vs/ps
        // load k, v tiles
        const float* kt = kb + (long)j * 64 * H_;
        const float* vt = vb + (long)j * 64 * H_;
        #pragma unroll
        for (int i = 0; i < 4; i++) {
            int idx = (tid + i * 256) * 4;
            int r = idx >> 6, c = idx & 63;
            *(float4*)&ks[r * KS_ + c] = *(const float4*)&kt[r * 64 + c];
            *(float4*)&vs[r * 64  + c] = *(const float4*)&vt[r * 64 + c];
        }
        __syncthreads();

        // S = q k^T  (4x4 per thread)
        float s[4][4] = {};
        #pragma unroll
        for (int d = 0; d < 64; d++) {
            float a[4], bb[4];
            #pragma unroll
            for (int i = 0; i < 4; i++)  a[i]  = qs[(row0 + i) * 64 + d];
            #pragma unroll
            for (int jj = 0; jj < 4; jj++) bb[jj] = ks[(col0 + jj) * KS_ + d];
            #pragma unroll
            for (int i = 0; i < 4; i++)
                #pragma unroll
                for (int jj = 0; jj < 4; jj++)
                    s[i][jj] += a[i] * bb[jj];
        }

        // scale + causal mask on diagonal tile
        const bool diag = (j == qi);
        #pragma unroll
        for (int i = 0; i < 4; i++)
            #pragma unroll
            for (int jj = 0; jj < 4; jj++) {
                s[i][jj] *= scale;
                if (diag && (col0 + jj) > (row0 + i)) s[i][jj] = -INFINITY;
            }

        // online softmax: new row max (reduce across 16 lanes of half-warp)
        float mnew[4];
        #pragma unroll
        for (int i = 0; i < 4; i++) {
            float mx = fmaxf(fmaxf(s[i][0], s[i][1]), fmaxf(s[i][2], s[i][3]));
            #pragma unroll
            for (int off = 1; off < 16; off <<= 1)
                mx = fmaxf(mx, __shfl_xor_sync(0xffffffffu, mx, off));
            mnew[i] = fmaxf(mx, m_i[i]);
        }
        float alpha[4];
        #pragma unroll
        for (int i = 0; i < 4; i++) {
            alpha[i] = __expf(m_i[i] - mnew[i]);
            m_i[i] = mnew[i];
        }
        // p = exp(s - m), row sums
        #pragma unroll
        for (int i = 0; i < 4; i++) {
            float rs = 0.0f;
            #pragma unroll
            for (int jj = 0; jj < 4; jj++) {
                float p = __expf(s[i][jj] - m_i[i]);
                s[i][jj] = p;
                rs += p;
            }
            #pragma unroll
            for (int off = 1; off < 16; off <<= 1)
                rs += __shfl_xor_sync(0xffffffffu, rs, off);
            l_i[i] = l_i[i] * alpha[i] + rs;
        }

        // stage p to smem for the O gemm
        #pragma unroll
        for (int i = 0; i < 4; i++)
            #pragma unroll
            for (int jj = 0; jj < 4; jj++)
                ps[(row0 + i) * PS_ + col0 + jj] = s[i][jj];

        // rescale accumulator
        #pragma unroll
        for (int i = 0; i < 4; i++)
            #pragma unroll
            for (int jj = 0; jj < 4; jj++)
                acc[i][jj] *= alpha[i];

        __syncthreads();

        // O += P @ V   (thread owns rows row0..+3, head-dims col0..+3)
        #pragma unroll
        for (int c = 0; c < 64; c++) {
            float p[4], vv[4];
            #pragma unroll
            for (int i = 0; i < 4; i++)  p[i]  = ps[(row0 + i) * PS_ + c];
            #pragma unroll
            for (int jj = 0; jj < 4; jj++) vv[jj] = vs[c * 64 + col0 + jj];
            #pragma unroll
            for (int i = 0; i < 4; i++)
                #pragma unroll
                for (int jj = 0; jj < 4; jj++)
                    acc[i][jj] += p[i] * vv[jj];
        }
    }

    // normalize and write out
    float* ob = out + ((long)b * T_ + (long)qi * 64) * H_;
    #pragma unroll
    for (int i = 0; i < 4; i++) {
        float inv = 1.0f / l_i[i];
        #pragma unroll
        for (int jj = 0; jj < 4; jj++)
            ob[(row0 + i) * H_ + col0 + jj] = acc[i][jj] * inv;
    }
}

// ---------------------------------------------------------------------------
extern "C" void kernel_launch(void* const* d_in, const int* in_sizes, int n_in,
                              void* d_out, int out_size)
{
    const float* x  = (const float*)d_in[0];
    const float* Wk = (const float*)d_in[1];
    const float* Wq = (const float*)d_in[2];
    const float* Wv = (const float*)d_in[3];
    float* out = (float*)d_out;

    // QKV projection: M = B*T = 32768 rows -> 512 row-tiles, 3 matrices
    dim3 pgrid((B_ * T_) / 64, 3);
    proj_kernel<<<pgrid, 256>>>(x, Wk, Wq, Wv);

    // Flash attention: (32 q-tiles, 16 batches)
    cudaFuncSetAttribute(attn_kernel, cudaFuncAttributeMaxDynamicSharedMemorySize,
                         ATTN_SMEM);
    attn_kernel<<<dim3(T_ / 64, B_), 256, ATTN_SMEM>>>(out);
}

// round 8
// speedup vs baseline: 2.2185x; 2.2185x over previous
#include <cuda_runtime.h>
#include <cuda_bf16.h>
#include <math.h>
#include <stdint.h>

// Problem constants
#define B_   16
#define T_   2048
#define E_   1024
#define H_   64

// Scratch for q,k,v projections (device globals: no allocation allowed)
__device__ float g_q[B_ * T_ * H_];
__device__ float g_k[B_ * T_ * H_];
__device__ float g_v[B_ * T_ * H_];

// ---------------------------------------------------------------------------
// helpers: tf32 convert + warp MMA m16n8k8 (tf32 inputs, fp32 accum)
// ---------------------------------------------------------------------------
__device__ __forceinline__ uint32_t f2t(float x) {
    uint32_t r;
    asm("cvt.rna.tf32.f32 %0, %1;" : "=r"(r) : "f"(x));
    return r;
}

__device__ __forceinline__ void mma_tf32(float c[4],
                                         uint32_t a0, uint32_t a1, uint32_t a2, uint32_t a3,
                                         uint32_t b0, uint32_t b1)
{
    asm volatile(
        "mma.sync.aligned.m16n8k8.row.col.f32.tf32.tf32.f32 "
        "{%0,%1,%2,%3}, {%4,%5,%6,%7}, {%8,%9}, {%0,%1,%2,%3};\n"
        : "+f"(c[0]), "+f"(c[1]), "+f"(c[2]), "+f"(c[3])
        : "r"(a0), "r"(a1), "r"(a2), "r"(a3), "r"(b0), "r"(b1));
}

// ---------------------------------------------------------------------------
// Kernel 1: QKV projection via 3xTF32 MMA.
// out = x @ W.  Block: 128 threads (4 warps). M-tile 128, N=64, K chunks of 32.
// 3xTF32: x = xh + xl, W = wh + wl; acc += xh*wh + xl*wh + xh*wl.
// smem strides: xs 36 (==4 mod 32, A-frag conflict-free),
//               ws 72 (==8 mod 32, B-frag conflict-free)
// ---------------------------------------------------------------------------
#define XS_S 36
#define WS_S 72
#define PROJ_SMEM ((128*XS_S*2 + 32*WS_S*2) * 4)   // 55296 B

__global__ __launch_bounds__(128) void proj_kernel(
    const float* __restrict__ x,
    const float* __restrict__ Wk,
    const float* __restrict__ Wq,
    const float* __restrict__ Wv)
{
    extern __shared__ uint32_t psm[];
    uint32_t* xh = psm;                    // 128*36
    uint32_t* xl = xh + 128 * XS_S;
    uint32_t* wh = xl + 128 * XS_S;        // 32*72
    uint32_t* wl = wh + 32 * WS_S;

    const float* W;
    float* out;
    if (blockIdx.y == 0)      { W = Wk; out = g_k; }
    else if (blockIdx.y == 1) { W = Wq; out = g_q; }
    else                      { W = Wv; out = g_v; }

    const int tid  = threadIdx.x;
    const int w    = tid >> 5;
    const int lane = tid & 31;
    const int g    = lane >> 2;
    const int t    = lane & 3;
    const long rowBase = (long)blockIdx.x * 128;

    float acc[2][8][4] = {};

    for (int k0 = 0; k0 < E_; k0 += 32) {
        __syncthreads();
        // load x chunk: 128 rows x 32 k  (1024 float4 / 128 thr = 8 each)
        #pragma unroll
        for (int i = 0; i < 8; i++) {
            int idx = tid + i * 128;
            int r = idx >> 3, c = (idx & 7) * 4;
            float4 v = *(const float4*)&x[(rowBase + r) * E_ + k0 + c];
            float hx = __uint_as_float(f2t(v.x));
            float hy = __uint_as_float(f2t(v.y));
            float hz = __uint_as_float(f2t(v.z));
            float hw = __uint_as_float(f2t(v.w));
            uint4 uh = make_uint4(__float_as_uint(hx), __float_as_uint(hy),
                                  __float_as_uint(hz), __float_as_uint(hw));
            uint4 ul = make_uint4(f2t(v.x - hx), f2t(v.y - hy),
                                  f2t(v.z - hz), f2t(v.w - hw));
            *(uint4*)&xh[r * XS_S + c] = uh;
            *(uint4*)&xl[r * XS_S + c] = ul;
        }
        // load W chunk: 32 k x 64 n (512 float4 / 128 = 4 each)
        #pragma unroll
        for (int i = 0; i < 4; i++) {
            int idx = tid + i * 128;
            int r = idx >> 4, c = (idx & 15) * 4;
            float4 v = *(const float4*)&W[(long)(k0 + r) * H_ + c];
            float hx = __uint_as_float(f2t(v.x));
            float hy = __uint_as_float(f2t(v.y));
            float hz = __uint_as_float(f2t(v.z));
            float hw = __uint_as_float(f2t(v.w));
            uint4 uh = make_uint4(__float_as_uint(hx), __float_as_uint(hy),
                                  __float_as_uint(hz), __float_as_uint(hw));
            uint4 ul = make_uint4(f2t(v.x - hx), f2t(v.y - hy),
                                  f2t(v.z - hz), f2t(v.w - hw));
            *(uint4*)&wh[r * WS_S + c] = uh;
            *(uint4*)&wl[r * WS_S + c] = ul;
        }
        __syncthreads();

        #pragma unroll
        for (int ks8 = 0; ks8 < 4; ks8++) {
            const int kk = ks8 * 8;
            uint32_t ah[2][4], al[2][4];
            #pragma unroll
            for (int mt = 0; mt < 2; mt++) {
                int r0 = mt * 64 + w * 16 + g;
                ah[mt][0] = xh[(r0    ) * XS_S + kk + t];
                ah[mt][1] = xh[(r0 + 8) * XS_S + kk + t];
                ah[mt][2] = xh[(r0    ) * XS_S + kk + t + 4];
                ah[mt][3] = xh[(r0 + 8) * XS_S + kk + t + 4];
                al[mt][0] = xl[(r0    ) * XS_S + kk + t];
                al[mt][1] = xl[(r0 + 8) * XS_S + kk + t];
                al[mt][2] = xl[(r0    ) * XS_S + kk + t + 4];
                al[mt][3] = xl[(r0 + 8) * XS_S + kk + t + 4];
            }
            #pragma unroll
            for (int nt = 0; nt < 8; nt++) {
                uint32_t bh0 = wh[(kk + t    ) * WS_S + nt * 8 + g];
                uint32_t bh1 = wh[(kk + t + 4) * WS_S + nt * 8 + g];
                uint32_t bl0 = wl[(kk + t    ) * WS_S + nt * 8 + g];
                uint32_t bl1 = wl[(kk + t + 4) * WS_S + nt * 8 + g];
                #pragma unroll
                for (int mt = 0; mt < 2; mt++) {
                    mma_tf32(acc[mt][nt], ah[mt][0], ah[mt][1], ah[mt][2], ah[mt][3], bh0, bh1);
                    mma_tf32(acc[mt][nt], al[mt][0], al[mt][1], al[mt][2], al[mt][3], bh0, bh1);
                    mma_tf32(acc[mt][nt], ah[mt][0], ah[mt][1], ah[mt][2], ah[mt][3], bl0, bl1);
                }
            }
        }
    }

    // store: rows rowBase + mt*64 + w*16 + g (+8), cols nt*8 + 2t (+1)
    #pragma unroll
    for (int mt = 0; mt < 2; mt++) {
        long r0 = rowBase + mt * 64 + w * 16 + g;
        #pragma unroll
        for (int nt = 0; nt < 8; nt++) {
            int c = nt * 8 + 2 * t;
            *(float2*)&out[(r0    ) * H_ + c] = make_float2(acc[mt][nt][0], acc[mt][nt][1]);
            *(float2*)&out[(r0 + 8) * H_ + c] = make_float2(acc[mt][nt][2], acc[mt][nt][3]);
        }
    }
}

// ---------------------------------------------------------------------------
// Kernel 2: causal flash attention, tf32 MMA.
// Block: 128 threads (4 warps). Q-tile 64 x K-tile 64. Warp w owns q-rows
// [w*16, w*16+16). S = Q K^T and O += P V both via m16n8k8.
// smem (uint32 tf32): qs[64][68], ks[64][68], vs[64][72], ps[64][68]
// ---------------------------------------------------------------------------
#define QS_S 68
#define KS_S 68
#define VS_S 72
#define PS_S 68
#define ATTN_SMEM ((64*QS_S + 64*KS_S + 64*VS_S + 64*PS_S) * 4)  // 70656 B

__global__ __launch_bounds__(128) void attn_kernel(float* __restrict__ out)
{
    extern __shared__ uint32_t asm_[];
    uint32_t* qs = asm_;
    uint32_t* ks = qs + 64 * QS_S;
    uint32_t* vs = ks + 64 * KS_S;
    uint32_t* ps = vs + 64 * VS_S;

    const int qi = blockIdx.x;     // query tile 0..31
    const int b  = blockIdx.y;     // batch
    const int tid  = threadIdx.x;
    const int w    = tid >> 5;
    const int lane = tid & 31;
    const int g    = lane >> 2;
    const int t    = lane & 3;

    const float* qb = g_q + ((long)b * T_ + (long)qi * 64) * H_;
    const float* kb = g_k + (long)b * T_ * H_;
    const float* vb = g_v + (long)b * T_ * H_;

    // load Q tile -> tf32 smem
    #pragma unroll
    for (int i = 0; i < 8; i++) {
        int idx = tid + i * 128;
        int r = idx >> 4, c = (idx & 15) * 4;
        float4 v = *(const float4*)&qb[r * H_ + c];
        *(uint4*)&qs[r * QS_S + c] =
            make_uint4(f2t(v.x), f2t(v.y), f2t(v.z), f2t(v.w));
    }

    float oc[8][4] = {};
    float m0 = -INFINITY, m1 = -INFINITY, l0 = 0.0f, l1 = 0.0f;
    const float scale = 0.125f;    // 64^-0.5

    const int row_g0 = qi * 64 + w * 16 + g;   // global q row of frag half 0
    const int row_g1 = row_g0 + 8;

    for (int j = 0; j <= qi; j++) {
        __syncthreads();
        const float* kt = kb + (long)j * 64 * H_;
        const float* vt = vb + (long)j * 64 * H_;
        #pragma unroll
        for (int i = 0; i < 8; i++) {
            int idx = tid + i * 128;
            int r = idx >> 4, c = (idx & 15) * 4;
            float4 kv = *(const float4*)&kt[r * H_ + c];
            float4 vv = *(const float4*)&vt[r * H_ + c];
            *(uint4*)&ks[r * KS_S + c] =
                make_uint4(f2t(kv.x), f2t(kv.y), f2t(kv.z), f2t(kv.w));
            *(uint4*)&vs[r * VS_S + c] =
                make_uint4(f2t(vv.x), f2t(vv.y), f2t(vv.z), f2t(vv.w));
        }
        __syncthreads();

        // ---- S = Q K^T ----
        float sc[8][4];
        #pragma unroll
        for (int nt = 0; nt < 8; nt++)
            #pragma unroll
            for (int ci = 0; ci < 4; ci++) sc[nt][ci] = 0.0f;

        #pragma unroll
        for (int ks8 = 0; ks8 < 8; ks8++) {
            const int kk = ks8 * 8;
            const int r0 = w * 16 + g;
            uint32_t a0 = qs[(r0    ) * QS_S + kk + t];
            uint32_t a1 = qs[(r0 + 8) * QS_S + kk + t];
            uint32_t a2 = qs[(r0    ) * QS_S + kk + t + 4];
            uint32_t a3 = qs[(r0 + 8) * QS_S + kk + t + 4];
            #pragma unroll
            for (int nt = 0; nt < 8; nt++) {
                uint32_t b0 = ks[(nt * 8 + g) * KS_S + kk + t];
                uint32_t b1 = ks[(nt * 8 + g) * KS_S + kk + t + 4];
                mma_tf32(sc[nt], a0, a1, a2, a3, b0, b1);
            }
        }

        // scale + causal mask (diagonal tile only)
        if (j == qi) {
            #pragma unroll
            for (int nt = 0; nt < 8; nt++) {
                int c0 = j * 64 + nt * 8 + 2 * t;
                sc[nt][0] = (c0     > row_g0) ? -INFINITY : sc[nt][0] * scale;
                sc[nt][1] = (c0 + 1 > row_g0) ? -INFINITY : sc[nt][1] * scale;
                sc[nt][2] = (c0     > row_g1) ? -INFINITY : sc[nt][2] * scale;
                sc[nt][3] = (c0 + 1 > row_g1) ? -INFINITY : sc[nt][3] * scale;
            }
        } else {
            #pragma unroll
            for (int nt = 0; nt < 8; nt++)
                #pragma unroll
                for (int ci = 0; ci < 4; ci++) sc[nt][ci] *= scale;
        }

        // ---- online softmax ----
        float mx0 = -INFINITY, mx1 = -INFINITY;
        #pragma unroll
        for (int nt = 0; nt < 8; nt++) {
            mx0 = fmaxf(mx0, fmaxf(sc[nt][0], sc[nt][1]));
            mx1 = fmaxf(mx1, fmaxf(sc[nt][2], sc[nt][3]));
        }
        #pragma unroll
        for (int off = 1; off < 4; off <<= 1) {
            mx0 = fmaxf(mx0, __shfl_xor_sync(0xffffffffu, mx0, off));
            mx1 = fmaxf(mx1, __shfl_xor_sync(0xffffffffu, mx1, off));
        }
        float mn0 = fmaxf(m0, mx0), mn1 = fmaxf(m1, mx1);
        float al0 = __expf(m0 - mn0), al1 = __expf(m1 - mn1);
        m0 = mn0; m1 = mn1;

        float rs0 = 0.0f, rs1 = 0.0f;
        #pragma unroll
        for (int nt = 0; nt < 8; nt++) {
            sc[nt][0] = __expf(sc[nt][0] - mn0);
            sc[nt][1] = __expf(sc[nt][1] - mn0);
            sc[nt][2] = __expf(sc[nt][2] - mn1);
            sc[nt][3] = __expf(sc[nt][3] - mn1);
            rs0 += sc[nt][0] + sc[nt][1];
            rs1 += sc[nt][2] + sc[nt][3];
        }
        #pragma unroll
        for (int off = 1; off < 4; off <<= 1) {
            rs0 += __shfl_xor_sync(0xffffffffu, rs0, off);
            rs1 += __shfl_xor_sync(0xffffffffu, rs1, off);
        }
        l0 = l0 * al0 + rs0;
        l1 = l1 * al1 + rs1;

        // rescale O, stage P (tf32) to smem
        #pragma unroll
        for (int nt = 0; nt < 8; nt++) {
            oc[nt][0] *= al0; oc[nt][1] *= al0;
            oc[nt][2] *= al1; oc[nt][3] *= al1;
            int r0 = w * 16 + g;
            int c  = nt * 8 + 2 * t;
            *(uint2*)&ps[(r0    ) * PS_S + c] = make_uint2(f2t(sc[nt][0]), f2t(sc[nt][1]));
            *(uint2*)&ps[(r0 + 8) * PS_S + c] = make_uint2(f2t(sc[nt][2]), f2t(sc[nt][3]));
        }
        __syncwarp();

        // ---- O += P V ----
        #pragma unroll
        for (int ks8 = 0; ks8 < 8; ks8++) {
            const int kk = ks8 * 8;
            const int r0 = w * 16 + g;
            uint32_t a0 = ps[(r0    ) * PS_S + kk + t];
            uint32_t a1 = ps[(r0 + 8) * PS_S + kk + t];
            uint32_t a2 = ps[(r0    ) * PS_S + kk + t + 4];
            uint32_t a3 = ps[(r0 + 8) * PS_S + kk + t + 4];
            #pragma unroll
            for (int nt = 0; nt < 8; nt++) {
                uint32_t b0 = vs[(kk + t    ) * VS_S + nt * 8 + g];
                uint32_t b1 = vs[(kk + t + 4) * VS_S + nt * 8 + g];
                mma_tf32(oc[nt], a0, a1, a2, a3, b0, b1);
            }
        }
    }

    // normalize + write out
    float inv0 = 1.0f / l0, inv1 = 1.0f / l1;
    float* ob = out + ((long)b * T_) * H_;
    #pragma unroll
    for (int nt = 0; nt < 8; nt++) {
        int c = nt * 8 + 2 * t;
        *(float2*)&ob[(long)row_g0 * H_ + c] =
            make_float2(oc[nt][0] * inv0, oc[nt][1] * inv0);
        *(float2*)&ob[(long)row_g1 * H_ + c] =
            make_float2(oc[nt][2] * inv1, oc[nt][3] * inv1);
    }
}

// ---------------------------------------------------------------------------
extern "C" void kernel_launch(void* const* d_in, const int* in_sizes, int n_in,
                              void* d_out, int out_size)
{
    const float* x  = (const float*)d_in[0];
    const float* Wk = (const float*)d_in[1];
    const float* Wq = (const float*)d_in[2];
    const float* Wv = (const float*)d_in[3];
    float* out = (float*)d_out;

    cudaFuncSetAttribute(proj_kernel, cudaFuncAttributeMaxDynamicSharedMemorySize,
                         PROJ_SMEM);
    cudaFuncSetAttribute(attn_kernel, cudaFuncAttributeMaxDynamicSharedMemorySize,
                         ATTN_SMEM);

    // QKV projection: M = B*T = 32768 -> 256 tiles of 128 rows, 3 matrices
    proj_kernel<<<dim3((B_ * T_) / 128, 3), 128, PROJ_SMEM>>>(x, Wk, Wq, Wv);

    // Flash attention: (32 q-tiles, 16 batches)
    attn_kernel<<<dim3(T_ / 64, B_), 128, ATTN_SMEM>>>(out);
}

// round 9
// speedup vs baseline: 2.2415x; 1.0104x over previous
#include <cuda_runtime.h>
#include <cuda_bf16.h>
#include <math.h>
#include <stdint.h>

// Problem constants
#define B_   16
#define T_   2048
#define E_   1024
#define H_   64

// Scratch for q,k,v projections (device globals: no allocation allowed)
__device__ float g_q[B_ * T_ * H_];
__device__ float g_k[B_ * T_ * H_];
__device__ float g_v[B_ * T_ * H_];

// ---------------------------------------------------------------------------
// helpers: tf32 convert + warp MMA m16n8k8 (tf32 inputs, fp32 accum)
// ---------------------------------------------------------------------------
__device__ __forceinline__ uint32_t f2t(float x) {
    uint32_t r;
    asm("cvt.rna.tf32.f32 %0, %1;" : "=r"(r) : "f"(x));
    return r;
}

__device__ __forceinline__ void mma_tf32(float c[4],
                                         uint32_t a0, uint32_t a1, uint32_t a2, uint32_t a3,
                                         uint32_t b0, uint32_t b1)
{
    asm volatile(
        "mma.sync.aligned.m16n8k8.row.col.f32.tf32.tf32.f32 "
        "{%0,%1,%2,%3}, {%4,%5,%6,%7}, {%8,%9}, {%0,%1,%2,%3};\n"
        : "+f"(c[0]), "+f"(c[1]), "+f"(c[2]), "+f"(c[3])
        : "r"(a0), "r"(a1), "r"(a2), "r"(a3), "r"(b0), "r"(b1));
}

// ---------------------------------------------------------------------------
// Kernel 1: FUSED QKV projection via 3xTF32 MMA.
// [k|q|v] = x @ [Wk|Wq|Wv].  Block: 128 threads (4 warps).
// M-tile 64, N = 192 (3 x 64), K chunks of 32. x loaded/split ONCE.
// 3xTF32: acc += xh*wh + xl*wh + xh*wl.
// smem strides: xs 36 (==4 mod 32, A-frag conflict-free),
//               ws 200 (==8 mod 32, B-frag conflict-free)
// ---------------------------------------------------------------------------
#define XS_S 36
#define WS_S 200
#define PROJ_SMEM ((64*XS_S*2 + 32*WS_S*2) * 4)   // 69632 B

__global__ __launch_bounds__(128) void proj_kernel(
    const float* __restrict__ x,
    const float* __restrict__ Wk,
    const float* __restrict__ Wq,
    const float* __restrict__ Wv)
{
    extern __shared__ uint32_t psm[];
    uint32_t* xh = psm;                    // 64*36
    uint32_t* xl = xh + 64 * XS_S;
    uint32_t* wh = xl + 64 * XS_S;         // 32*200
    uint32_t* wl = wh + 32 * WS_S;

    const int tid  = threadIdx.x;
    const int w    = tid >> 5;
    const int lane = tid & 31;
    const int g    = lane >> 2;
    const int t    = lane & 3;
    const long rowBase = (long)blockIdx.x * 64;

    float acc[24][4] = {};

    for (int k0 = 0; k0 < E_; k0 += 32) {
        __syncthreads();
        // load x chunk: 64 rows x 32 k  (512 float4 / 128 thr = 4 each)
        #pragma unroll
        for (int i = 0; i < 4; i++) {
            int idx = tid + i * 128;
            int r = idx >> 3, c = (idx & 7) * 4;
            float4 v = *(const float4*)&x[(rowBase + r) * E_ + k0 + c];
            float hx = __uint_as_float(f2t(v.x));
            float hy = __uint_as_float(f2t(v.y));
            float hz = __uint_as_float(f2t(v.z));
            float hw = __uint_as_float(f2t(v.w));
            *(uint4*)&xh[r * XS_S + c] =
                make_uint4(__float_as_uint(hx), __float_as_uint(hy),
                           __float_as_uint(hz), __float_as_uint(hw));
            *(uint4*)&xl[r * XS_S + c] =
                make_uint4(f2t(v.x - hx), f2t(v.y - hy),
                           f2t(v.z - hz), f2t(v.w - hw));
        }
        // load W chunk: 32 k x 192 n  (1536 float4 / 128 thr = 12 each)
        #pragma unroll
        for (int i = 0; i < 12; i++) {
            int idx = tid + i * 128;       // 0..1535
            int r   = idx / 48;            // 0..31 (48 float4 per 192-col row)
            int c   = (idx % 48) * 4;      // 0..188, never straddles a 64-col slice
            const float* Wsel = (c < 64) ? Wk : ((c < 128) ? Wq : Wv);
            float4 v = *(const float4*)&Wsel[(long)(k0 + r) * H_ + (c & 63)];
            float hx = __uint_as_float(f2t(v.x));
            float hy = __uint_as_float(f2t(v.y));
            float hz = __uint_as_float(f2t(v.z));
            float hw = __uint_as_float(f2t(v.w));
            *(uint4*)&wh[r * WS_S + c] =
                make_uint4(__float_as_uint(hx), __float_as_uint(hy),
                           __float_as_uint(hz), __float_as_uint(hw));
            *(uint4*)&wl[r * WS_S + c] =
                make_uint4(f2t(v.x - hx), f2t(v.y - hy),
                           f2t(v.z - hz), f2t(v.w - hw));
        }
        __syncthreads();

        #pragma unroll
        for (int ks8 = 0; ks8 < 4; ks8++) {
            const int kk = ks8 * 8;
            const int r0 = w * 16 + g;
            uint32_t ah0 = xh[(r0    ) * XS_S + kk + t];
            uint32_t ah1 = xh[(r0 + 8) * XS_S + kk + t];
            uint32_t ah2 = xh[(r0    ) * XS_S + kk + t + 4];
            uint32_t ah3 = xh[(r0 + 8) * XS_S + kk + t + 4];
            uint32_t al0 = xl[(r0    ) * XS_S + kk + t];
            uint32_t al1 = xl[(r0 + 8) * XS_S + kk + t];
            uint32_t al2 = xl[(r0    ) * XS_S + kk + t + 4];
            uint32_t al3 = xl[(r0 + 8) * XS_S + kk + t + 4];
            #pragma unroll
            for (int nt = 0; nt < 24; nt++) {
                uint32_t bh0 = wh[(kk + t    ) * WS_S + nt * 8 + g];
                uint32_t bh1 = wh[(kk + t + 4) * WS_S + nt * 8 + g];
                uint32_t bl0 = wl[(kk + t    ) * WS_S + nt * 8 + g];
                uint32_t bl1 = wl[(kk + t + 4) * WS_S + nt * 8 + g];
                mma_tf32(acc[nt], ah0, ah1, ah2, ah3, bh0, bh1);
                mma_tf32(acc[nt], al0, al1, al2, al3, bh0, bh1);
                mma_tf32(acc[nt], ah0, ah1, ah2, ah3, bl0, bl1);
            }
        }
    }

    // store: nt 0..7 -> g_k, 8..15 -> g_q, 16..23 -> g_v
    const long r0 = rowBase + w * 16 + g;
    #pragma unroll
    for (int nt = 0; nt < 24; nt++) {
        float* o = (nt < 8) ? g_k : ((nt < 16) ? g_q : g_v);
        int c = (nt & 7) * 8 + 2 * t;
        *(float2*)&o[(r0    ) * H_ + c] = make_float2(acc[nt][0], acc[nt][1]);
        *(float2*)&o[(r0 + 8) * H_ + c] = make_float2(acc[nt][2], acc[nt][3]);
    }
}

// ---------------------------------------------------------------------------
// Kernel 2: causal flash attention, tf32 MMA.
// Block: 256 threads (8 warps). Q-tile 128 x K-tile 64. Warp w owns q-rows
// [w*16, w*16+16). S = Q K^T and O += P V both via m16n8k8.
// smem (uint32 tf32): qs[128][68], ks[64][68], vs[64][72], ps[128][68]
// qi is reverse-mapped so the most-work blocks launch first.
// ---------------------------------------------------------------------------
#define QS_S 68
#define KS_S 68
#define VS_S 72
#define PS_S 68
#define ATTN_SMEM ((128*QS_S + 64*KS_S + 64*VS_S + 128*PS_S) * 4)  // 105472 B

__global__ __launch_bounds__(256) void attn_kernel(float* __restrict__ out)
{
    extern __shared__ uint32_t asm_[];
    uint32_t* qs = asm_;                   // 128 x QS_S
    uint32_t* ks = qs + 128 * QS_S;        // 64 x KS_S
    uint32_t* vs = ks + 64 * KS_S;         // 64 x VS_S
    uint32_t* ps = vs + 64 * VS_S;         // 128 x PS_S

    const int qi = (T_ / 128 - 1) - blockIdx.x;   // 15..0, big tiles first
    const int b  = blockIdx.y;
    const int tid  = threadIdx.x;
    const int w    = tid >> 5;             // 0..7
    const int lane = tid & 31;
    const int g    = lane >> 2;
    const int t    = lane & 3;

    const float* qb = g_q + ((long)b * T_ + (long)qi * 128) * H_;
    const float* kb = g_k + (long)b * T_ * H_;
    const float* vb = g_v + (long)b * T_ * H_;

    // load Q tile (128 x 64) -> tf32 smem: 2048 float4 / 256 thr = 8 each
    #pragma unroll
    for (int i = 0; i < 8; i++) {
        int idx = tid + i * 256;
        int r = idx >> 4, c = (idx & 15) * 4;
        float4 v = *(const float4*)&qb[r * H_ + c];
        *(uint4*)&qs[r * QS_S + c] =
            make_uint4(f2t(v.x), f2t(v.y), f2t(v.z), f2t(v.w));
    }

    float oc[8][4] = {};
    float m0 = -INFINITY, m1 = -INFINITY, l0 = 0.0f, l1 = 0.0f;
    const float scale = 0.125f;            // 64^-0.5

    const int r0s   = w * 16 + g;               // smem row of frag half 0
    const int row_g0 = qi * 128 + r0s;          // global q row of frag half 0
    const int row_g1 = row_g0 + 8;

    const int jmax = 2 * qi + 1;
    for (int j = 0; j <= jmax; j++) {
        __syncthreads();
        // load K,V tiles (64 x 64 each): 1024 float4 / 256 thr = 4 each
        const float* kt = kb + (long)j * 64 * H_;
        const float* vt = vb + (long)j * 64 * H_;
        #pragma unroll
        for (int i = 0; i < 4; i++) {
            int idx = tid + i * 256;
            int r = idx >> 4, c = (idx & 15) * 4;
            float4 kv = *(const float4*)&kt[r * H_ + c];
            float4 vv = *(const float4*)&vt[r * H_ + c];
            *(uint4*)&ks[r * KS_S + c] =
                make_uint4(f2t(kv.x), f2t(kv.y), f2t(kv.z), f2t(kv.w));
            *(uint4*)&vs[r * VS_S + c] =
                make_uint4(f2t(vv.x), f2t(vv.y), f2t(vv.z), f2t(vv.w));
        }
        __syncthreads();

        // ---- S = Q K^T ----
        float sc[8][4];
        #pragma unroll
        for (int nt = 0; nt < 8; nt++)
            #pragma unroll
            for (int ci = 0; ci < 4; ci++) sc[nt][ci] = 0.0f;

        #pragma unroll
        for (int ks8 = 0; ks8 < 8; ks8++) {
            const int kk = ks8 * 8;
            uint32_t a0 = qs[(r0s    ) * QS_S + kk + t];
            uint32_t a1 = qs[(r0s + 8) * QS_S + kk + t];
            uint32_t a2 = qs[(r0s    ) * QS_S + kk + t + 4];
            uint32_t a3 = qs[(r0s + 8) * QS_S + kk + t + 4];
            #pragma unroll
            for (int nt = 0; nt < 8; nt++) {
                uint32_t b0 = ks[(nt * 8 + g) * KS_S + kk + t];
                uint32_t b1 = ks[(nt * 8 + g) * KS_S + kk + t + 4];
                mma_tf32(sc[nt], a0, a1, a2, a3, b0, b1);
            }
        }

        // scale + causal mask (only when this key tile can exceed our rows)
        if (j * 64 + 63 > row_g0) {
            #pragma unroll
            for (int nt = 0; nt < 8; nt++) {
                int c0 = j * 64 + nt * 8 + 2 * t;
                sc[nt][0] = (c0     > row_g0) ? -INFINITY : sc[nt][0] * scale;
                sc[nt][1] = (c0 + 1 > row_g0) ? -INFINITY : sc[nt][1] * scale;
                sc[nt][2] = (c0     > row_g1) ? -INFINITY : sc[nt][2] * scale;
                sc[nt][3] = (c0 + 1 > row_g1) ? -INFINITY : sc[nt][3] * scale;
            }
        } else {
            #pragma unroll
            for (int nt = 0; nt < 8; nt++)
                #pragma unroll
                for (int ci = 0; ci < 4; ci++) sc[nt][ci] *= scale;
        }

        // ---- online softmax ----
        float mx0 = -INFINITY, mx1 = -INFINITY;
        #pragma unroll
        for (int nt = 0; nt < 8; nt++) {
            mx0 = fmaxf(mx0, fmaxf(sc[nt][0], sc[nt][1]));
            mx1 = fmaxf(mx1, fmaxf(sc[nt][2], sc[nt][3]));
        }
        #pragma unroll
        for (int off = 1; off < 4; off <<= 1) {
            mx0 = fmaxf(mx0, __shfl_xor_sync(0xffffffffu, mx0, off));
            mx1 = fmaxf(mx1, __shfl_xor_sync(0xffffffffu, mx1, off));
        }
        float mn0 = fmaxf(m0, mx0), mn1 = fmaxf(m1, mx1);
        float al0 = __expf(m0 - mn0), al1 = __expf(m1 - mn1);
        m0 = mn0; m1 = mn1;

        float rs0 = 0.0f, rs1 = 0.0f;
        #pragma unroll
        for (int nt = 0; nt < 8; nt++) {
            sc[nt][0] = __expf(sc[nt][0] - mn0);
            sc[nt][1] = __expf(sc[nt][1] - mn0);
            sc[nt][2] = __expf(sc[nt][2] - mn1);
            sc[nt][3] = __expf(sc[nt][3] - mn1);
            rs0 += sc[nt][0] + sc[nt][1];
            rs1 += sc[nt][2] + sc[nt][3];
        }
        #pragma unroll
        for (int off = 1; off < 4; off <<= 1) {
            rs0 += __shfl_xor_sync(0xffffffffu, rs0, off);
            rs1 += __shfl_xor_sync(0xffffffffu, rs1, off);
        }
        l0 = l0 * al0 + rs0;
        l1 = l1 * al1 + rs1;

        // rescale O, stage P (tf32) to smem (per-warp rows: __syncwarp enough)
        #pragma unroll
        for (int nt = 0; nt < 8; nt++) {
            oc[nt][0] *= al0; oc[nt][1] *= al0;
            oc[nt][2] *= al1; oc[nt][3] *= al1;
            int c = nt * 8 + 2 * t;
            *(uint2*)&ps[(r0s    ) * PS_S + c] = make_uint2(f2t(sc[nt][0]), f2t(sc[nt][1]));
            *(uint2*)&ps[(r0s + 8) * PS_S + c] = make_uint2(f2t(sc[nt][2]), f2t(sc[nt][3]));
        }
        __syncwarp();

        // ---- O += P V ----
        #pragma unroll
        for (int ks8 = 0; ks8 < 8; ks8++) {
            const int kk = ks8 * 8;
            uint32_t a0 = ps[(r0s    ) * PS_S + kk + t];
            uint32_t a1 = ps[(r0s + 8) * PS_S + kk + t];
            uint32_t a2 = ps[(r0s    ) * PS_S + kk + t + 4];
            uint32_t a3 = ps[(r0s + 8) * PS_S + kk + t + 4];
            #pragma unroll
            for (int nt = 0; nt < 8; nt++) {
                uint32_t b0 = vs[(kk + t    ) * VS_S + nt * 8 + g];
                uint32_t b1 = vs[(kk + t + 4) * VS_S + nt * 8 + g];
                mma_tf32(oc[nt], a0, a1, a2, a3, b0, b1);
            }
        }
    }

    // normalize + write out
    float inv0 = 1.0f / l0, inv1 = 1.0f / l1;
    float* ob = out + ((long)b * T_) * H_;
    #pragma unroll
    for (int nt = 0; nt < 8; nt++) {
        int c = nt * 8 + 2 * t;
        *(float2*)&ob[(long)row_g0 * H_ + c] =
            make_float2(oc[nt][0] * inv0, oc[nt][1] * inv0);
        *(float2*)&ob[(long)row_g1 * H_ + c] =
            make_float2(oc[nt][2] * inv1, oc[nt][3] * inv1);
    }
}

// ---------------------------------------------------------------------------
extern "C" void kernel_launch(void* const* d_in, const int* in_sizes, int n_in,
                              void* d_out, int out_size)
{
    const float* x  = (const float*)d_in[0];
    const float* Wk = (const float*)d_in[1];
    const float* Wq = (const float*)d_in[2];
    const float* Wv = (const float*)d_in[3];
    float* out = (float*)d_out;

    cudaFuncSetAttribute(proj_kernel, cudaFuncAttributeMaxDynamicSharedMemorySize,
                         PROJ_SMEM);
    cudaFuncSetAttribute(attn_kernel, cudaFuncAttributeMaxDynamicSharedMemorySize,
                         ATTN_SMEM);

    // Fused QKV projection: M = B*T = 32768 -> 512 tiles of 64 rows
    proj_kernel<<<(B_ * T_) / 64, 128, PROJ_SMEM>>>(x, Wk, Wq, Wv);

    // Flash attention: (16 q-tiles of 128, 16 batches)
    attn_kernel<<<dim3(T_ / 128, B_), 256, ATTN_SMEM>>>(out);
}